// round 6
// baseline (speedup 1.0000x reference)
#include <cuda_runtime.h>

// R6: concurrency + streaming-eviction test.
// Evidence: LDG, MUFU+MLP4, and cp.async.bulk all cap at ~2.2TB/s with every
// pipe <28% busy -> path-independent, nothing saturated. MLP_p1 1->4 bought
// 17% (R1->R3). Push the only axis that has ever moved the number:
//   - EPT=8 front-batched LDG.128 per thread, zero predicates (exact cover),
//     4KB in flight per warp (2x R3).
//   - __ldcs/__stcs: x/out are single-use streams; evict-first in L2.
//
// Math (fixed since R1): RZ phases cancel in |amp|^2 (params unused); the CNOT
// chain is XOR-linear; out = [c1c2c3, c0c1, c0c1c2, c0c1c2c3], c_j = cos(x_j).

#define BLOCK 256
#define EPT   8   // float4 per thread

__global__ void __launch_bounds__(BLOCK)
_VariationalQHead_65481071396152_kernel(const float4* __restrict__ x,
                                        float4* __restrict__ out)
{
    int base = blockIdx.x * (BLOCK * EPT) + threadIdx.x;

    float4 v[EPT];
#pragma unroll
    for (int k = 0; k < EPT; k++)
        v[k] = __ldcs(&x[base + k * BLOCK]);      // streaming, evict-first

#pragma unroll
    for (int k = 0; k < EPT; k++) {
        float c0 = __cosf(v[k].x);
        float c1 = __cosf(v[k].y);
        float c2 = __cosf(v[k].z);
        float c3 = __cosf(v[k].w);
        float c01  = c0 * c1;
        float c012 = c01 * c2;
        float4 o;
        o.x = c1 * c2 * c3;
        o.y = c01;
        o.z = c012;
        o.w = c012 * c3;
        __stcs(&out[base + k * BLOCK], o);        // streaming store
    }
}

// Generic fallback for any residue (dataset is 2^20 rows -> unused there).
__global__ void _VQH_tail_kernel(const float4* __restrict__ x,
                                 float4* __restrict__ out, int start, int n)
{
    int i = start + blockIdx.x * blockDim.x + threadIdx.x;
    if (i < n) {
        float4 v = __ldcs(&x[i]);
        float c0 = __cosf(v.x), c1 = __cosf(v.y), c2 = __cosf(v.z), c3 = __cosf(v.w);
        float c01 = c0 * c1, c012 = c01 * c2;
        float4 o = make_float4(c1 * c2 * c3, c01, c012, c012 * c3);
        __stcs(&out[i], o);
    }
}

extern "C" void kernel_launch(void* const* d_in, const int* in_sizes, int n_in,
                              void* d_out, int out_size)
{
    const float4* x = (const float4*)d_in[0];   // x: [B,4] float32
    float4* out = (float4*)d_out;               // out: [B,4] float32
    int n4 = in_sizes[0] / 4;                   // batch rows (float4 count)

    int per_block = BLOCK * EPT;
    int grid = n4 / per_block;                  // full tiles, no predicates
    if (grid > 0)
        _VariationalQHead_65481071396152_kernel<<<grid, BLOCK>>>(x, out);

    int rem_start = grid * per_block;
    int rem = n4 - rem_start;
    if (rem > 0)
        _VQH_tail_kernel<<<(rem + 255) / 256, 256>>>(x, out, rem_start, n4);
}